// round 15
// baseline (speedup 1.0000x reference)
#include <cuda_runtime.h>
#include <cuda_fp16.h>
#include <math.h>
#include <stdint.h>

#define NN 100000
#define TT2 2

// ---------------- scratch ----------------
__device__ __align__(8) float2 g_nd[NN];     // (agg, deg) fused
__device__ float g_degmax;
__device__ float g_sum_s, g_sum_a, g_sum_ss, g_sum_aa, g_sum_sa;
__device__ __align__(16) __half g_score_h[NN];   // f16 score image

// Compacted per-lane B fragments (102) — layout identical to round 14.
#define NFRAG 102
__device__ __align__(16) uint2 g_wfrag[NFRAG * 32];

#define HM_R 0b00111
#define HM_M 0b11111
#define HM_P 0b11100

// ---------------- helpers ----------------
__device__ __forceinline__ uint32_t smem_u32(const void* p) {
    uint32_t a; asm("{ .reg .u64 t; cvta.to.shared.u64 t, %1; cvt.u32.u64 %0, t; }" : "=r"(a) : "l"(p));
    return a;
}
__device__ __forceinline__ void ldm4(uint32_t* a, uint32_t addr) {
    asm volatile("ldmatrix.sync.aligned.m8n8.x4.shared.b16 {%0,%1,%2,%3}, [%4];"
        : "=r"(a[0]), "=r"(a[1]), "=r"(a[2]), "=r"(a[3]) : "r"(addr));
}
__device__ __forceinline__ void mma16816(float* d, const uint32_t* a, uint32_t b0, uint32_t b1,
                                         const float* c) {
    asm("mma.sync.aligned.m16n8k16.row.col.f32.f16.f16.f32 "
        "{%0,%1,%2,%3}, {%4,%5,%6,%7}, {%8,%9}, {%10,%11,%12,%13};"
        : "=f"(d[0]), "=f"(d[1]), "=f"(d[2]), "=f"(d[3])
        : "r"(a[0]), "r"(a[1]), "r"(a[2]), "r"(a[3]), "r"(b0), "r"(b1),
          "f"(c[0]), "f"(c[1]), "f"(c[2]), "f"(c[3]));
}
__device__ __forceinline__ uint32_t phh(float hi, float lo) {
    uint32_t r; asm("cvt.rn.f16x2.f32 %0, %1, %2;" : "=r"(r) : "f"(hi), "f"(lo)); return r;
}
__device__ __forceinline__ uint32_t pack_h2(float a, float b) {
    uint32_t r; asm("cvt.rn.f16x2.f32 %0, %1, %2;" : "=r"(r) : "f"(b), "f"(a)); return r;
}
__device__ __forceinline__ uint32_t relu2(uint32_t v) {
    uint32_t r, z = 0u;
    asm("max.f16x2 %0, %1, %2;" : "=r"(r) : "r"(v), "r"(z));
    return r;
}
__device__ __forceinline__ float sigf(float v) { return 1.0f / (1.0f + __expf(-v)); }

__device__ __forceinline__ void cvt_pair(uint32_t (&afp)[4], const float (&d0)[4], const float (&d1)[4]) {
    afp[0] = relu2(phh(d0[1], d0[0]));
    afp[1] = relu2(phh(d0[3], d0[2]));
    afp[2] = relu2(phh(d1[1], d1[0]));
    afp[3] = relu2(phh(d1[3], d1[2]));
}
__device__ __forceinline__ void cp16(uint32_t saddr, const void* gptr) {
    asm volatile("cp.async.cg.shared.global [%0], [%1], 16;" :: "r"(saddr), "l"(gptr) : "memory");
}
#define CP_COMMIT() asm volatile("cp.async.commit_group;" ::: "memory")
#define CP_WAIT0()  asm volatile("cp.async.wait_group 0;" ::: "memory")

// ---------------- weight fragment prep (identical layout to round 14) ----------------
__device__ float wv(int sec, int hl, int k, int n,
    const float* Rsw, const float* Rsb, const float* Rhw, const float* Rhb,
    const float* Rew, const float* Reb,
    const float* Psw, const float* Psb, const float* Phw, const float* Phb,
    const float* Pew, const float* Peb) {
    if (sec == 0) {
        int fk = -1;
        if (k < 5) fk = k;
        else if (k >= 8 && k < 13) fk = k - 3;
        if (n < 35) {
            if (fk >= 0) return Rsw[n*10 + fk];
            if (k == 5) return Rsb[n];
        } else if (n >= 36 && n < 71) {
            int m = n - 36;
            if (fk >= 0) return Psw[m*10 + (9 - fk)];
            if (k == 5) return Psb[m];
        }
        return 0.f;
    }
    if (sec == 1) {
        if (n < 35) {
            if (k < 35) return Rhw[hl*1225 + n*35 + k];
            if (k == 35) return Rhb[hl*35 + n];
        } else if (n >= 36 && n < 71) {
            int m = n - 36;
            if (k >= 36 && k < 71) return Phw[hl*1225 + m*35 + (k - 36)];
            if (k == 35) return Phb[hl*35 + m];
        }
        return 0.f;
    }
    if (n < 5) {
        if (k < 35) return Rew[n*35 + k];
        if (k == 35) return Reb[n];
    } else if (n >= 8 && n < 13) {
        int m = n - 8;
        if (k >= 36 && k < 71) return Pew[m*35 + (k - 36)];
        if (k == 35) return Peb[m];
    }
    return 0.f;
}

__device__ int kth_bit(int mask, int rank) {
    for (int k = 0; k < 5; k++)
        if (mask & (1 << k)) { if (rank == 0) return k; rank--; }
    return 0;
}

__global__ void k_prep(const float* score, int N,
    const float* Rsw, const float* Rsb, const float* Rhw, const float* Rhb,
    const float* Rew, const float* Reb,
    const float* Psw, const float* Psb, const float* Phw, const float* Phb,
    const float* Pew, const float* Peb) {
    const int hb[9] = {0, 3, 6, 9, 12, 17, 20, 23, 26};
    int i0 = blockIdx.x * blockDim.x + threadIdx.x;
    for (int i = i0; i < N; i += blockDim.x * gridDim.x)
        g_score_h[i] = __float2half_rn(score[i]);
    for (int i = i0; i < NFRAG * 32; i += blockDim.x * gridDim.x) {
        int f = i >> 5, l = i & 31;
        int sec, hl = 0, kt = 0, nt;
        if (f < 9)       { sec = 0; nt = f; }
        else if (f < 96) {
            int g = f - 9; sec = 1; hl = g / 29; int w = g % 29;
            nt = 8;
            for (int q = 0; q < 8; q++) if (w < hb[q + 1]) { nt = q; break; }
            int mask = (nt < 4) ? HM_R : (nt == 4) ? HM_M : HM_P;
            kt = kth_bit(mask, w - hb[nt]);
        } else {
            int g = f - 96; sec = 2;
            if (g < 3) { nt = 0; kt = kth_bit(HM_R, g); }
            else       { nt = 1; kt = kth_bit(HM_P, g - 3); }
        }
        int n  = nt * 8 + (l >> 2);
        int k0 = kt * 16 + 2 * (l & 3);
        float w0 = wv(sec, hl, k0,     n, Rsw,Rsb,Rhw,Rhb,Rew,Reb,Psw,Psb,Phw,Phb,Pew,Peb);
        float w1 = wv(sec, hl, k0 + 1, n, Rsw,Rsb,Rhw,Rhb,Rew,Reb,Psw,Psb,Phw,Phb,Pew,Peb);
        float w8 = wv(sec, hl, k0 + 8, n, Rsw,Rsb,Rhw,Rhb,Rew,Reb,Psw,Psb,Phw,Phb,Pew,Peb);
        float w9 = wv(sec, hl, k0 + 9, n, Rsw,Rsb,Rhw,Rhb,Rew,Reb,Psw,Psb,Phw,Phb,Pew,Peb);
        uint2 o;
        o.x = pack_h2(w0, w1);
        o.y = pack_h2(w8, w9);
        g_wfrag[i] = o;
    }
}

__global__ void k_noop() {}

// ---------------- edge kernel: smem-resident f16 score, owner-lane scatter ----------------
#define SC_BYTES 200000
#define WF_OFF   SC_BYTES
#define WF_BYTES (NFRAG * 32 * 8)            // 26112
#define XD_OFF   (WF_OFF + WF_BYTES)         // 226112
#define SMEMB    (XD_OFF + 6 * 1024)         // 232256  (<= 232448)

// one fused hidden layer (identical math to round 14)
__device__ __forceinline__ void hidden_layer(const uint2* __restrict__ wfl, int& fi,
        const uint32_t (&ai)[TT2][5][4], uint32_t (&ao)[TT2][5][4], uint32_t inj) {
    #pragma unroll
    for (int ntp = 0; ntp < 4; ntp++) {
        float D2[TT2][2][4];
        #pragma unroll
        for (int h2 = 0; h2 < 2; h2++) {
            const int nt = 2 * ntp + h2;
            const int mask = (nt < 4) ? HM_R : (nt == 4) ? HM_M : HM_P;
            #pragma unroll
            for (int tt = 0; tt < TT2; tt++)
                #pragma unroll
                for (int q = 0; q < 4; q++) D2[tt][h2][q] = 0.f;
            #pragma unroll
            for (int kt = 0; kt < 5; kt++) {
                if (mask & (1 << kt)) {
                    uint2 b = wfl[fi * 32]; fi++;
                    #pragma unroll
                    for (int tt = 0; tt < TT2; tt++)
                        mma16816(D2[tt][h2], ai[tt][kt], b.x, b.y, D2[tt][h2]);
                }
            }
        }
        #pragma unroll
        for (int tt = 0; tt < TT2; tt++) {
            cvt_pair(ao[tt][ntp], D2[tt][0], D2[tt][1]);
            if (ntp == 2) { ao[tt][2][0] |= inj; ao[tt][2][1] |= inj; }
        }
    }
    {
        float D1[TT2][4];
        #pragma unroll
        for (int tt = 0; tt < TT2; tt++)
            #pragma unroll
            for (int q = 0; q < 4; q++) D1[tt][q] = 0.f;
        #pragma unroll
        for (int kt = 0; kt < 5; kt++) {
            if (HM_P & (1 << kt)) {
                uint2 b = wfl[fi * 32]; fi++;
                #pragma unroll
                for (int tt = 0; tt < TT2; tt++)
                    mma16816(D1[tt], ai[tt][kt], b.x, b.y, D1[tt]);
            }
        }
        #pragma unroll
        for (int tt = 0; tt < TT2; tt++) {
            ao[tt][4][0] = relu2(phh(D1[tt][1], D1[tt][0]));
            ao[tt][4][1] = relu2(phh(D1[tt][3], D1[tt][2]));
            ao[tt][4][2] = 0u;
            ao[tt][4][3] = 0u;
        }
    }
}

// stage one tile's end-layer fragments into ds (16 rows x 12 f32)
__device__ __forceinline__ void stage_ds(float* ds, const float (&d)[2][4], int r0, int c0) {
    if (c0 < 5) {   // c0 in {0,2,4}; cols 5 and 11 are scratch
        *(float2*)(ds + r0*12 + c0)           = make_float2(d[0][0], d[0][1]);
        *(float2*)(ds + (r0+8)*12 + c0)       = make_float2(d[0][2], d[0][3]);
        *(float2*)(ds + r0*12 + 6 + c0)       = make_float2(d[1][0], d[1][1]);
        *(float2*)(ds + (r0+8)*12 + 6 + c0)   = make_float2(d[1][2], d[1][3]);
    }
}

__global__ void __launch_bounds__(192, 1)
k_edges(const int* __restrict__ edge_idx, const float* __restrict__ outcome,
        int E, int ngroups) {
    extern __shared__ char sm[];
    const int tid = threadIdx.x;
    const int wid = tid >> 5, lane = tid & 31;
    const uint32_t smb = smem_u32(sm);

    // stage f16 score (200KB) + weight frags (26KB) into smem
    for (int i = tid; i < SC_BYTES / 16; i += 192)
        cp16(smb + i * 16, (const char*)g_score_h + i * 16);
    for (int i = tid; i < WF_BYTES / 16; i += 192)
        cp16(smb + WF_OFF + i * 16, (const char*)g_wfrag + i * 16);
    CP_COMMIT(); CP_WAIT0();
    __syncthreads();

    const unsigned short* sc16 = (const unsigned short*)sm;
    const uint2* wfl = ((const uint2*)(sm + WF_OFF)) + lane;
    char* xd = sm + XD_OFF + wid * 1024;
    __half* xt = (__half*)xd;
    float*  ds = (float*)xd;
    const uint32_t xt_ldm = smem_u32(xt) + (lane & 15) * 32 + (lane >> 4) * 16;

    const int r = lane & 15, hh = lane >> 4;
    const int r0 = lane >> 2, c0 = 2 * (lane & 3);
    const uint32_t inj = ((lane & 3) == 1) ? 0x3C000000u : 0u;
    const int gw = blockIdx.x * 6 + wid, gstride = gridDim.x * 6;

    if (gw >= ngroups) return;

    // prologue: load own edge's idx row + outcome
    int iv[10];
    bool pos;
    {
        const int e = gw * 32 + hh * 16 + r;
        const int ec = (e < E) ? e : E - 1;
        const int2* ep = (const int2*)(edge_idx + (long long)ec * 10);
        #pragma unroll
        for (int i = 0; i < 5; i++) { int2 a = ep[i]; iv[2*i] = a.x; iv[2*i+1] = a.y; }
        pos = outcome[ec] > 0.f;
    }

    for (int p = gw; p < ngroups; p += gstride) {
        const int pn = p + gstride;
        const int eown = p * 32 + hh * 16 + r;

        // qi = feature-order node ids (reversal folded via SELs)
        int qi[10];
        #pragma unroll
        for (int k = 0; k < 10; k++) qi[k] = pos ? iv[k] : iv[9 - k];

        // gather from smem f16 score, build own xt row (2 x STS.128)
        {
            uint32_t h[10];
            #pragma unroll
            for (int k = 0; k < 10; k++) h[k] = (uint32_t)sc16[qi[k]];
            uint4 w0, w1;
            w0.x = h[0] | (h[1] << 16);
            w0.y = h[2] | (h[3] << 16);
            w0.z = h[4] | (0x3C00u << 16);       // bias 1.0h at k5
            w0.w = 0u;
            w1.x = h[5] | (h[6] << 16);
            w1.y = h[7] | (h[8] << 16);
            w1.z = h[9];
            w1.w = 0u;
            uint4* rowp = (uint4*)(xt + (hh * 16 + r) * 16);
            rowp[0] = w0;
            rowp[1] = w1;
        }
        __syncwarp();

        // ldmatrix both tiles
        uint32_t a0[4], a1[4];
        ldm4(a0, xt_ldm);
        ldm4(a1, xt_ldm + 512);
        __syncwarp();

        // prefetch next group's idx + outcome (lands during MLP chain)
        int ivN[10];
        bool posN = false;
        if (pn < ngroups) {
            const int eN = pn * 32 + hh * 16 + r;
            const int ec = (eN < E) ? eN : E - 1;
            const int2* ep = (const int2*)(edge_idx + (long long)ec * 10);
            #pragma unroll
            for (int i = 0; i < 5; i++) { int2 a = ep[i]; ivN[2*i] = a.x; ivN[2*i+1] = a.y; }
            posN = outcome[ec] > 0.f;
        }

        // ---- layer 1 -> afA ----
        uint32_t afA[TT2][5][4], afB[TT2][5][4];
        {
            const float z[4] = {0.f, 0.f, 0.f, 0.f};
            #pragma unroll
            for (int ntp = 0; ntp < 4; ntp++) {
                float D2[TT2][2][4];
                #pragma unroll
                for (int h2 = 0; h2 < 2; h2++) {
                    uint2 b = wfl[(2 * ntp + h2) * 32];
                    mma16816(D2[0][h2], a0, b.x, b.y, z);
                    mma16816(D2[1][h2], a1, b.x, b.y, z);
                }
                #pragma unroll
                for (int tt = 0; tt < TT2; tt++) {
                    cvt_pair(afA[tt][ntp], D2[tt][0], D2[tt][1]);
                    if (ntp == 2) { afA[tt][2][0] |= inj; afA[tt][2][1] |= inj; }
                }
            }
            {
                float D1[TT2][4];
                uint2 b = wfl[8 * 32];
                mma16816(D1[0], a0, b.x, b.y, z);
                mma16816(D1[1], a1, b.x, b.y, z);
                #pragma unroll
                for (int tt = 0; tt < TT2; tt++) {
                    afA[tt][4][0] = relu2(phh(D1[tt][1], D1[tt][0]));
                    afA[tt][4][1] = relu2(phh(D1[tt][3], D1[tt][2]));
                    afA[tt][4][2] = 0u;
                    afA[tt][4][3] = 0u;
                }
            }
        }

        int fi = 9;
        hidden_layer(wfl, fi, afA, afB, inj);    // H1
        hidden_layer(wfl, fi, afB, afA, inj);    // H2
        hidden_layer(wfl, fi, afA, afB, inj);    // H3

        // ---- end layer from afB ----
        float de[TT2][2][4];
        #pragma unroll
        for (int nt = 0; nt < 2; nt++) {
            const int mask = (nt == 0) ? HM_R : HM_P;
            #pragma unroll
            for (int tt = 0; tt < TT2; tt++)
                #pragma unroll
                for (int q = 0; q < 4; q++) de[tt][nt][q] = 0.f;
            #pragma unroll
            for (int kt = 0; kt < 5; kt++) {
                if (mask & (1 << kt)) {
                    uint2 b = wfl[fi * 32]; fi++;
                    #pragma unroll
                    for (int tt = 0; tt < TT2; tt++)
                        mma16816(de[tt][nt], afB[tt][kt], b.x, b.y, de[tt][nt]);
                }
            }
        }

        // ---- owner-lane scatter, two phases (tile 0 then tile 1) ----
        #pragma unroll
        for (int tt = 0; tt < 2; tt++) {
            __syncwarp();
            stage_ds(ds, de[tt], r0, c0);
            __syncwarp();
            if (hh == tt && eown < E) {
                float v[10];
                #pragma unroll
                for (int j = 0; j < 5; j++) { v[j] = ds[r*12 + j]; v[5+j] = ds[r*12 + 6 + j]; }
                #pragma unroll
                for (int j = 0; j < 5; j++) {
                    const int nR = pos ? qi[j]     : qi[4 - j];
                    const int nP = pos ? qi[5 + j] : qi[9 - j];
                    atomicAdd(&g_nd[nR], make_float2( sigf(v[j]),     1.f));
                    atomicAdd(&g_nd[nP], make_float2(-sigf(v[5 + j]), 1.f));
                }
            }
        }
        __syncwarp();

        // rotate pipeline state
        #pragma unroll
        for (int k = 0; k < 10; k++) iv[k] = ivN[k];
        pos = posN;
    }
}

// ---------------- epilogue ----------------
__global__ void k_init(int n) {
    int i = blockIdx.x * blockDim.x + threadIdx.x;
    if (i < n) g_nd[i] = make_float2(0.f, 0.f);
    if (i == 0) {
        g_degmax = 0.f;
        g_sum_s = 0.f; g_sum_a = 0.f; g_sum_ss = 0.f; g_sum_aa = 0.f; g_sum_sa = 0.f;
    }
}

__global__ void k_reduce(const float* __restrict__ score, int n) {
    __shared__ float w0[8], w1[8], w2[8], w3[8], w4[8], wm[8];
    int i = blockIdx.x * 256 + threadIdx.x;
    float s = 0.f, a = 0.f, d = 0.f;
    if (i < n) { s = score[i]; float2 nd = g_nd[i]; a = nd.x; d = nd.y; }
    float ss = s*s, aa = a*a, sa = s*a;
    #pragma unroll
    for (int o = 16; o > 0; o >>= 1) {
        s += __shfl_down_sync(~0u, s, o);  a += __shfl_down_sync(~0u, a, o);
        ss += __shfl_down_sync(~0u, ss, o); aa += __shfl_down_sync(~0u, aa, o);
        sa += __shfl_down_sync(~0u, sa, o); d = fmaxf(d, __shfl_down_sync(~0u, d, o));
    }
    int lane = threadIdx.x & 31, wd = threadIdx.x >> 5;
    if (lane == 0) { w0[wd]=s; w1[wd]=a; w2[wd]=ss; w3[wd]=aa; w4[wd]=sa; wm[wd]=d; }
    __syncthreads();
    if (wd == 0) {
        s  = (lane < 8) ? w0[lane] : 0.f;  a  = (lane < 8) ? w1[lane] : 0.f;
        ss = (lane < 8) ? w2[lane] : 0.f;  aa = (lane < 8) ? w3[lane] : 0.f;
        sa = (lane < 8) ? w4[lane] : 0.f;  d  = (lane < 8) ? wm[lane] : 0.f;
        #pragma unroll
        for (int o = 4; o > 0; o >>= 1) {
            s += __shfl_down_sync(~0u, s, o);  a += __shfl_down_sync(~0u, a, o);
            ss += __shfl_down_sync(~0u, ss, o); aa += __shfl_down_sync(~0u, aa, o);
            sa += __shfl_down_sync(~0u, sa, o); d = fmaxf(d, __shfl_down_sync(~0u, d, o));
        }
        if (lane == 0) {
            atomicAdd(&g_sum_s, s);  atomicAdd(&g_sum_a, a);
            atomicAdd(&g_sum_ss, ss); atomicAdd(&g_sum_aa, aa);
            atomicAdd(&g_sum_sa, sa);
            atomicMax((int*)&g_degmax, __float_as_int(d));
        }
    }
}

__global__ void k_final(const float* __restrict__ score, float* __restrict__ out, int n) {
    int i = blockIdx.x * blockDim.x + threadIdx.x;
    if (i < n) {
        float scale = 2.0f / g_degmax;
        float mean  = (g_sum_s + scale * g_sum_a) / (float)n;
        float sumsq = g_sum_ss + 2.f * scale * g_sum_sa + scale * scale * g_sum_aa;
        float norm  = sqrtf(fmaxf(sumsq - (float)n * mean * mean, 1e-30f));
        float t = score[i] + scale * g_nd[i].x;
        out[i] = (t - mean) / norm;
    }
}

extern "C" void kernel_launch(void* const* d_in, const int* in_sizes, int n_in,
                              void* d_out, int out_size) {
    const float* score    = (const float*)d_in[0];
    const int*   edge_idx = (const int*)  d_in[1];
    const float* outcome  = (const float*)d_in[2];
    const float* Rsw = (const float*)d_in[3];
    const float* Rsb = (const float*)d_in[4];
    const float* Rhw = (const float*)d_in[5];
    const float* Rhb = (const float*)d_in[6];
    const float* Rew = (const float*)d_in[7];
    const float* Reb = (const float*)d_in[8];
    const float* Psw = (const float*)d_in[9];
    const float* Psb = (const float*)d_in[10];
    const float* Phw = (const float*)d_in[11];
    const float* Phb = (const float*)d_in[12];
    const float* Pew = (const float*)d_in[13];
    const float* Peb = (const float*)d_in[14];

    const int N = in_sizes[0];
    const int E = in_sizes[2];
    const int ngroups = (E + 31) / 32;

    cudaFuncSetAttribute(k_edges, cudaFuncAttributeMaxDynamicSharedMemorySize, SMEMB);

    const int nb = (N + 255) / 256;
    k_init<<<nb, 256>>>(N);                                   // 0
    k_prep<<<26, 256>>>(score, N, Rsw, Rsb, Rhw, Rhb, Rew, Reb,
                        Psw, Psb, Phw, Phb, Pew, Peb);        // 1
    k_noop<<<1, 32>>>();                                      // 2
    k_edges<<<152, 192, SMEMB>>>(edge_idx, outcome, E, ngroups);  // 3 (ncu slot)
    k_reduce<<<nb, 256>>>(score, N);                          // 4
    k_final<<<nb, 256>>>(score, (float*)d_out, N);            // 5
}

// round 16
// speedup vs baseline: 1.2251x; 1.2251x over previous
#include <cuda_runtime.h>
#include <cuda_fp16.h>
#include <math.h>
#include <stdint.h>

#define NN 100000
#define TT2 2

// ---------------- scratch ----------------
__device__ __align__(8) float2 g_nd[NN];     // (agg, deg) fused
__device__ float g_degmax;
__device__ float g_sum_s, g_sum_a, g_sum_ss, g_sum_aa, g_sum_sa;
__device__ __align__(16) __half g_score_h[NN];   // f16 score image

// Compacted per-lane B fragments (102) — layout identical to round 14.
// f0..8 = L1, f9..95 = hidden (29/layer), f96..101 = end
#define NFRAG 102
__device__ __align__(16) uint2 g_wfrag[NFRAG * 32];

#define HM_R 0b00111
#define HM_M 0b11111
#define HM_P 0b11100

// ---------------- helpers ----------------
__device__ __forceinline__ uint32_t smem_u32(const void* p) {
    uint32_t a; asm("{ .reg .u64 t; cvta.to.shared.u64 t, %1; cvt.u32.u64 %0, t; }" : "=r"(a) : "l"(p));
    return a;
}
__device__ __forceinline__ void ldm4(uint32_t* a, uint32_t addr) {
    asm volatile("ldmatrix.sync.aligned.m8n8.x4.shared.b16 {%0,%1,%2,%3}, [%4];"
        : "=r"(a[0]), "=r"(a[1]), "=r"(a[2]), "=r"(a[3]) : "r"(addr));
}
__device__ __forceinline__ void mma16816(float* d, const uint32_t* a, uint32_t b0, uint32_t b1,
                                         const float* c) {
    asm("mma.sync.aligned.m16n8k16.row.col.f32.f16.f16.f32 "
        "{%0,%1,%2,%3}, {%4,%5,%6,%7}, {%8,%9}, {%10,%11,%12,%13};"
        : "=f"(d[0]), "=f"(d[1]), "=f"(d[2]), "=f"(d[3])
        : "r"(a[0]), "r"(a[1]), "r"(a[2]), "r"(a[3]), "r"(b0), "r"(b1),
          "f"(c[0]), "f"(c[1]), "f"(c[2]), "f"(c[3]));
}
__device__ __forceinline__ uint32_t phh(float hi, float lo) {
    uint32_t r; asm("cvt.rn.f16x2.f32 %0, %1, %2;" : "=r"(r) : "f"(hi), "f"(lo)); return r;
}
__device__ __forceinline__ uint32_t pack_h2(float a, float b) {
    uint32_t r; asm("cvt.rn.f16x2.f32 %0, %1, %2;" : "=r"(r) : "f"(b), "f"(a)); return r;
}
__device__ __forceinline__ uint32_t relu2(uint32_t v) {
    uint32_t r, z = 0u;
    asm("max.f16x2 %0, %1, %2;" : "=r"(r) : "r"(v), "r"(z));
    return r;
}
__device__ __forceinline__ float sigf(float v) { return 1.0f / (1.0f + __expf(-v)); }

__device__ __forceinline__ void cvt_pair(uint32_t (&afp)[4], const float (&d0)[4], const float (&d1)[4]) {
    afp[0] = relu2(phh(d0[1], d0[0]));
    afp[1] = relu2(phh(d0[3], d0[2]));
    afp[2] = relu2(phh(d1[1], d1[0]));
    afp[3] = relu2(phh(d1[3], d1[2]));
}
__device__ __forceinline__ void cp16(uint32_t saddr, const void* gptr) {
    asm volatile("cp.async.cg.shared.global [%0], [%1], 16;" :: "r"(saddr), "l"(gptr) : "memory");
}
#define CP_COMMIT() asm volatile("cp.async.commit_group;" ::: "memory")
#define CP_WAIT0()  asm volatile("cp.async.wait_group 0;" ::: "memory")

// ---------------- weight fragment prep (identical layout to round 14) ----------------
__device__ float wv(int sec, int hl, int k, int n,
    const float* Rsw, const float* Rsb, const float* Rhw, const float* Rhb,
    const float* Rew, const float* Reb,
    const float* Psw, const float* Psb, const float* Phw, const float* Phb,
    const float* Pew, const float* Peb) {
    if (sec == 0) {
        int fk = -1;
        if (k < 5) fk = k;
        else if (k >= 8 && k < 13) fk = k - 3;
        if (n < 35) {
            if (fk >= 0) return Rsw[n*10 + fk];
            if (k == 5) return Rsb[n];
        } else if (n >= 36 && n < 71) {
            int m = n - 36;
            if (fk >= 0) return Psw[m*10 + (9 - fk)];
            if (k == 5) return Psb[m];
        }
        return 0.f;
    }
    if (sec == 1) {
        if (n < 35) {
            if (k < 35) return Rhw[hl*1225 + n*35 + k];
            if (k == 35) return Rhb[hl*35 + n];
        } else if (n >= 36 && n < 71) {
            int m = n - 36;
            if (k >= 36 && k < 71) return Phw[hl*1225 + m*35 + (k - 36)];
            if (k == 35) return Phb[hl*35 + m];
        }
        return 0.f;
    }
    if (n < 5) {
        if (k < 35) return Rew[n*35 + k];
        if (k == 35) return Reb[n];
    } else if (n >= 8 && n < 13) {
        int m = n - 8;
        if (k >= 36 && k < 71) return Pew[m*35 + (k - 36)];
        if (k == 35) return Peb[m];
    }
    return 0.f;
}

__device__ int kth_bit(int mask, int rank) {
    for (int k = 0; k < 5; k++)
        if (mask & (1 << k)) { if (rank == 0) return k; rank--; }
    return 0;
}

__global__ void k_prep(const float* score, int N,
    const float* Rsw, const float* Rsb, const float* Rhw, const float* Rhb,
    const float* Rew, const float* Reb,
    const float* Psw, const float* Psb, const float* Phw, const float* Phb,
    const float* Pew, const float* Peb) {
    const int hb[9] = {0, 3, 6, 9, 12, 17, 20, 23, 26};
    int i0 = blockIdx.x * blockDim.x + threadIdx.x;
    for (int i = i0; i < N; i += blockDim.x * gridDim.x)
        g_score_h[i] = __float2half_rn(score[i]);
    for (int i = i0; i < NFRAG * 32; i += blockDim.x * gridDim.x) {
        int f = i >> 5, l = i & 31;
        int sec, hl = 0, kt = 0, nt;
        if (f < 9)       { sec = 0; nt = f; }
        else if (f < 96) {
            int g = f - 9; sec = 1; hl = g / 29; int w = g % 29;
            nt = 8;
            for (int q = 0; q < 8; q++) if (w < hb[q + 1]) { nt = q; break; }
            int mask = (nt < 4) ? HM_R : (nt == 4) ? HM_M : HM_P;
            kt = kth_bit(mask, w - hb[nt]);
        } else {
            int g = f - 96; sec = 2;
            if (g < 3) { nt = 0; kt = kth_bit(HM_R, g); }
            else       { nt = 1; kt = kth_bit(HM_P, g - 3); }
        }
        int n  = nt * 8 + (l >> 2);
        int k0 = kt * 16 + 2 * (l & 3);
        float w0 = wv(sec, hl, k0,     n, Rsw,Rsb,Rhw,Rhb,Rew,Reb,Psw,Psb,Phw,Phb,Pew,Peb);
        float w1 = wv(sec, hl, k0 + 1, n, Rsw,Rsb,Rhw,Rhb,Rew,Reb,Psw,Psb,Phw,Phb,Pew,Peb);
        float w8 = wv(sec, hl, k0 + 8, n, Rsw,Rsb,Rhw,Rhb,Rew,Reb,Psw,Psb,Phw,Phb,Pew,Peb);
        float w9 = wv(sec, hl, k0 + 9, n, Rsw,Rsb,Rhw,Rhb,Rew,Reb,Psw,Psb,Phw,Phb,Pew,Peb);
        uint2 o;
        o.x = pack_h2(w0, w1);
        o.y = pack_h2(w8, w9);
        g_wfrag[i] = o;
    }
}

__global__ void k_noop() {}

// ---------------- edge kernel: smem score + 8 warps; hidden frags smem, L1/end frags __ldg ----------------
#define SC_BYTES 200000
#define WF_OFF   SC_BYTES
#define WF_SM_BYTES (87 * 32 * 8)            // 22272 (hidden frags f9..95)
#define XD_OFF   (WF_OFF + WF_SM_BYTES)      // 222272
#define NWARP 8
#define SMEMB    (XD_OFF + NWARP * 1024)     // 230464 <= 232448

// one fused hidden layer; wfh = smem hidden frags (cursor fi starts at 0)
__device__ __forceinline__ void hidden_layer(const uint2* __restrict__ wfh, int& fi,
        const uint32_t (&ai)[TT2][5][4], uint32_t (&ao)[TT2][5][4], uint32_t inj) {
    #pragma unroll
    for (int ntp = 0; ntp < 4; ntp++) {
        float D2[TT2][2][4];
        #pragma unroll
        for (int h2 = 0; h2 < 2; h2++) {
            const int nt = 2 * ntp + h2;
            const int mask = (nt < 4) ? HM_R : (nt == 4) ? HM_M : HM_P;
            #pragma unroll
            for (int tt = 0; tt < TT2; tt++)
                #pragma unroll
                for (int q = 0; q < 4; q++) D2[tt][h2][q] = 0.f;
            #pragma unroll
            for (int kt = 0; kt < 5; kt++) {
                if (mask & (1 << kt)) {
                    uint2 b = wfh[fi * 32]; fi++;
                    #pragma unroll
                    for (int tt = 0; tt < TT2; tt++)
                        mma16816(D2[tt][h2], ai[tt][kt], b.x, b.y, D2[tt][h2]);
                }
            }
        }
        #pragma unroll
        for (int tt = 0; tt < TT2; tt++) {
            cvt_pair(ao[tt][ntp], D2[tt][0], D2[tt][1]);
            if (ntp == 2) { ao[tt][2][0] |= inj; ao[tt][2][1] |= inj; }
        }
    }
    {
        float D1[TT2][4];
        #pragma unroll
        for (int tt = 0; tt < TT2; tt++)
            #pragma unroll
            for (int q = 0; q < 4; q++) D1[tt][q] = 0.f;
        #pragma unroll
        for (int kt = 0; kt < 5; kt++) {
            if (HM_P & (1 << kt)) {
                uint2 b = wfh[fi * 32]; fi++;
                #pragma unroll
                for (int tt = 0; tt < TT2; tt++)
                    mma16816(D1[tt], ai[tt][kt], b.x, b.y, D1[tt]);
            }
        }
        #pragma unroll
        for (int tt = 0; tt < TT2; tt++) {
            ao[tt][4][0] = relu2(phh(D1[tt][1], D1[tt][0]));
            ao[tt][4][1] = relu2(phh(D1[tt][3], D1[tt][2]));
            ao[tt][4][2] = 0u;
            ao[tt][4][3] = 0u;
        }
    }
}

// stage one tile's end-layer fragments into ds (16 rows x 12 f32)
__device__ __forceinline__ void stage_ds(float* ds, const float (&d)[2][4], int r0, int c0) {
    if (c0 < 5) {
        *(float2*)(ds + r0*12 + c0)           = make_float2(d[0][0], d[0][1]);
        *(float2*)(ds + (r0+8)*12 + c0)       = make_float2(d[0][2], d[0][3]);
        *(float2*)(ds + r0*12 + 6 + c0)       = make_float2(d[1][0], d[1][1]);
        *(float2*)(ds + (r0+8)*12 + 6 + c0)   = make_float2(d[1][2], d[1][3]);
    }
}

__global__ void __launch_bounds__(NWARP * 32, 1)
k_edges(const int* __restrict__ edge_idx, const float* __restrict__ outcome,
        int E, int ngroups) {
    extern __shared__ char sm[];
    const int tid = threadIdx.x;
    const int wid = tid >> 5, lane = tid & 31;
    const uint32_t smb = smem_u32(sm);
    const int nthr = NWARP * 32;

    // stage f16 score (200KB) + hidden frags (22KB) into smem
    for (int i = tid; i < SC_BYTES / 16; i += nthr)
        cp16(smb + i * 16, (const char*)g_score_h + i * 16);
    for (int i = tid; i < WF_SM_BYTES / 16; i += nthr)
        cp16(smb + WF_OFF + i * 16, (const char*)(g_wfrag + 9 * 32) + i * 16);
    CP_COMMIT(); CP_WAIT0();
    __syncthreads();

    const unsigned short* sc16 = (const unsigned short*)sm;
    const uint2* wfh = ((const uint2*)(sm + WF_OFF)) + lane;   // hidden frags
    char* xd = sm + XD_OFF + wid * 1024;
    __half* xt = (__half*)xd;
    float*  ds = (float*)xd;
    const uint32_t xt_ldm = smem_u32(xt) + (lane & 15) * 32 + (lane >> 4) * 16;

    const int r = lane & 15, hh = lane >> 4;
    const int r0 = lane >> 2, c0 = 2 * (lane & 3);
    const uint32_t inj = ((lane & 3) == 1) ? 0x3C000000u : 0u;
    const int gw = blockIdx.x * NWARP + wid, gstride = gridDim.x * NWARP;

    if (gw >= ngroups) return;

    // prologue: own edge's idx + outcome
    int iv[10];
    bool pos;
    {
        const int e = gw * 32 + hh * 16 + r;
        const int ec = (e < E) ? e : E - 1;
        const int2* ep = (const int2*)(edge_idx + (long long)ec * 10);
        #pragma unroll
        for (int i = 0; i < 5; i++) { int2 a = ep[i]; iv[2*i] = a.x; iv[2*i+1] = a.y; }
        pos = outcome[ec] > 0.f;
    }

    for (int p = gw; p < ngroups; p += gstride) {
        const int pn = p + gstride;
        const int eown = p * 32 + hh * 16 + r;

        int qi[10];
        #pragma unroll
        for (int k = 0; k < 10; k++) qi[k] = pos ? iv[k] : iv[9 - k];

        // gather from smem f16 score, build own xt row (2 x STS.128)
        {
            uint32_t h[10];
            #pragma unroll
            for (int k = 0; k < 10; k++) h[k] = (uint32_t)sc16[qi[k]];
            uint4 w0, w1;
            w0.x = h[0] | (h[1] << 16);
            w0.y = h[2] | (h[3] << 16);
            w0.z = h[4] | (0x3C00u << 16);       // bias 1.0h at k5
            w0.w = 0u;
            w1.x = h[5] | (h[6] << 16);
            w1.y = h[7] | (h[8] << 16);
            w1.z = h[9];
            w1.w = 0u;
            uint4* rowp = (uint4*)(xt + (hh * 16 + r) * 16);
            rowp[0] = w0;
            rowp[1] = w1;
        }
        __syncwarp();

        uint32_t a0[4], a1[4];
        ldm4(a0, xt_ldm);
        ldm4(a1, xt_ldm + 512);
        __syncwarp();

        // prefetch next group's idx + outcome (lands during MLP chain)
        int ivN[10];
        bool posN = false;
        if (pn < ngroups) {
            const int eN = pn * 32 + hh * 16 + r;
            const int ec = (eN < E) ? eN : E - 1;
            const int2* ep = (const int2*)(edge_idx + (long long)ec * 10);
            #pragma unroll
            for (int i = 0; i < 5; i++) { int2 a = ep[i]; ivN[2*i] = a.x; ivN[2*i+1] = a.y; }
            posN = outcome[ec] > 0.f;
        }

        // ---- layer 1 -> afA (frags via __ldg, L1D-resident) ----
        uint32_t afA[TT2][5][4], afB[TT2][5][4];
        {
            const float z[4] = {0.f, 0.f, 0.f, 0.f};
            #pragma unroll
            for (int ntp = 0; ntp < 4; ntp++) {
                float D2[TT2][2][4];
                #pragma unroll
                for (int h2 = 0; h2 < 2; h2++) {
                    uint2 b = __ldg(&g_wfrag[(2 * ntp + h2) * 32 + lane]);
                    mma16816(D2[0][h2], a0, b.x, b.y, z);
                    mma16816(D2[1][h2], a1, b.x, b.y, z);
                }
                #pragma unroll
                for (int tt = 0; tt < TT2; tt++) {
                    cvt_pair(afA[tt][ntp], D2[tt][0], D2[tt][1]);
                    if (ntp == 2) { afA[tt][2][0] |= inj; afA[tt][2][1] |= inj; }
                }
            }
            {
                float D1[TT2][4];
                uint2 b = __ldg(&g_wfrag[8 * 32 + lane]);
                mma16816(D1[0], a0, b.x, b.y, z);
                mma16816(D1[1], a1, b.x, b.y, z);
                #pragma unroll
                for (int tt = 0; tt < TT2; tt++) {
                    afA[tt][4][0] = relu2(phh(D1[tt][1], D1[tt][0]));
                    afA[tt][4][1] = relu2(phh(D1[tt][3], D1[tt][2]));
                    afA[tt][4][2] = 0u;
                    afA[tt][4][3] = 0u;
                }
            }
        }

        int fi = 0;
        hidden_layer(wfh, fi, afA, afB, inj);    // H1
        hidden_layer(wfh, fi, afB, afA, inj);    // H2
        hidden_layer(wfh, fi, afA, afB, inj);    // H3

        // ---- end layer from afB (frags via __ldg) ----
        float de[TT2][2][4];
        int fe = 96;
        #pragma unroll
        for (int nt = 0; nt < 2; nt++) {
            const int mask = (nt == 0) ? HM_R : HM_P;
            #pragma unroll
            for (int tt = 0; tt < TT2; tt++)
                #pragma unroll
                for (int q = 0; q < 4; q++) de[tt][nt][q] = 0.f;
            #pragma unroll
            for (int kt = 0; kt < 5; kt++) {
                if (mask & (1 << kt)) {
                    uint2 b = __ldg(&g_wfrag[fe * 32 + lane]); fe++;
                    #pragma unroll
                    for (int tt = 0; tt < TT2; tt++)
                        mma16816(de[tt][nt], afB[tt][kt], b.x, b.y, de[tt][nt]);
                }
            }
        }

        // ---- owner-lane scatter, two phases ----
        #pragma unroll
        for (int tt = 0; tt < 2; tt++) {
            __syncwarp();
            stage_ds(ds, de[tt], r0, c0);
            __syncwarp();
            if (hh == tt && eown < E) {
                float v[10];
                #pragma unroll
                for (int j = 0; j < 5; j++) { v[j] = ds[r*12 + j]; v[5+j] = ds[r*12 + 6 + j]; }
                #pragma unroll
                for (int j = 0; j < 5; j++) {
                    const int nR = pos ? qi[j]     : qi[4 - j];
                    const int nP = pos ? qi[5 + j] : qi[9 - j];
                    atomicAdd(&g_nd[nR], make_float2( sigf(v[j]),     1.f));
                    atomicAdd(&g_nd[nP], make_float2(-sigf(v[5 + j]), 1.f));
                }
            }
        }
        __syncwarp();

        #pragma unroll
        for (int k = 0; k < 10; k++) iv[k] = ivN[k];
        pos = posN;
    }
}

// ---------------- epilogue ----------------
__global__ void k_init(int n) {
    int i = blockIdx.x * blockDim.x + threadIdx.x;
    if (i < n) g_nd[i] = make_float2(0.f, 0.f);
    if (i == 0) {
        g_degmax = 0.f;
        g_sum_s = 0.f; g_sum_a = 0.f; g_sum_ss = 0.f; g_sum_aa = 0.f; g_sum_sa = 0.f;
    }
}

__global__ void k_reduce(const float* __restrict__ score, int n) {
    __shared__ float w0[8], w1[8], w2[8], w3[8], w4[8], wm[8];
    int i = blockIdx.x * 256 + threadIdx.x;
    float s = 0.f, a = 0.f, d = 0.f;
    if (i < n) { s = score[i]; float2 nd = g_nd[i]; a = nd.x; d = nd.y; }
    float ss = s*s, aa = a*a, sa = s*a;
    #pragma unroll
    for (int o = 16; o > 0; o >>= 1) {
        s += __shfl_down_sync(~0u, s, o);  a += __shfl_down_sync(~0u, a, o);
        ss += __shfl_down_sync(~0u, ss, o); aa += __shfl_down_sync(~0u, aa, o);
        sa += __shfl_down_sync(~0u, sa, o); d = fmaxf(d, __shfl_down_sync(~0u, d, o));
    }
    int lane = threadIdx.x & 31, wd = threadIdx.x >> 5;
    if (lane == 0) { w0[wd]=s; w1[wd]=a; w2[wd]=ss; w3[wd]=aa; w4[wd]=sa; wm[wd]=d; }
    __syncthreads();
    if (wd == 0) {
        s  = (lane < 8) ? w0[lane] : 0.f;  a  = (lane < 8) ? w1[lane] : 0.f;
        ss = (lane < 8) ? w2[lane] : 0.f;  aa = (lane < 8) ? w3[lane] : 0.f;
        sa = (lane < 8) ? w4[lane] : 0.f;  d  = (lane < 8) ? wm[lane] : 0.f;
        #pragma unroll
        for (int o = 4; o > 0; o >>= 1) {
            s += __shfl_down_sync(~0u, s, o);  a += __shfl_down_sync(~0u, a, o);
            ss += __shfl_down_sync(~0u, ss, o); aa += __shfl_down_sync(~0u, aa, o);
            sa += __shfl_down_sync(~0u, sa, o); d = fmaxf(d, __shfl_down_sync(~0u, d, o));
        }
        if (lane == 0) {
            atomicAdd(&g_sum_s, s);  atomicAdd(&g_sum_a, a);
            atomicAdd(&g_sum_ss, ss); atomicAdd(&g_sum_aa, aa);
            atomicAdd(&g_sum_sa, sa);
            atomicMax((int*)&g_degmax, __float_as_int(d));
        }
    }
}

__global__ void k_final(const float* __restrict__ score, float* __restrict__ out, int n) {
    int i = blockIdx.x * blockDim.x + threadIdx.x;
    if (i < n) {
        float scale = 2.0f / g_degmax;
        float mean  = (g_sum_s + scale * g_sum_a) / (float)n;
        float sumsq = g_sum_ss + 2.f * scale * g_sum_sa + scale * scale * g_sum_aa;
        float norm  = sqrtf(fmaxf(sumsq - (float)n * mean * mean, 1e-30f));
        float t = score[i] + scale * g_nd[i].x;
        out[i] = (t - mean) / norm;
    }
}

extern "C" void kernel_launch(void* const* d_in, const int* in_sizes, int n_in,
                              void* d_out, int out_size) {
    const float* score    = (const float*)d_in[0];
    const int*   edge_idx = (const int*)  d_in[1];
    const float* outcome  = (const float*)d_in[2];
    const float* Rsw = (const float*)d_in[3];
    const float* Rsb = (const float*)d_in[4];
    const float* Rhw = (const float*)d_in[5];
    const float* Rhb = (const float*)d_in[6];
    const float* Rew = (const float*)d_in[7];
    const float* Reb = (const float*)d_in[8];
    const float* Psw = (const float*)d_in[9];
    const float* Psb = (const float*)d_in[10];
    const float* Phw = (const float*)d_in[11];
    const float* Phb = (const float*)d_in[12];
    const float* Pew = (const float*)d_in[13];
    const float* Peb = (const float*)d_in[14];

    const int N = in_sizes[0];
    const int E = in_sizes[2];
    const int ngroups = (E + 31) / 32;

    cudaFuncSetAttribute(k_edges, cudaFuncAttributeMaxDynamicSharedMemorySize, SMEMB);

    const int nb = (N + 255) / 256;
    k_init<<<nb, 256>>>(N);                                   // 0
    k_prep<<<26, 256>>>(score, N, Rsw, Rsb, Rhw, Rhb, Rew, Reb,
                        Psw, Psb, Phw, Phb, Pew, Peb);        // 1
    k_noop<<<1, 32>>>();                                      // 2
    k_edges<<<152, NWARP * 32, SMEMB>>>(edge_idx, outcome, E, ngroups);  // 3 (ncu slot)
    k_reduce<<<nb, 256>>>(score, N);                          // 4
    k_final<<<nb, 256>>>(score, (float*)d_out, N);            // 5
}